// round 3
// baseline (speedup 1.0000x reference)
#include <cuda_runtime.h>
#include <cuda_bf16.h>
#include <mma.h>

using namespace nvcuda;

#define NBLK  128
#define NTHR  256
#define BN    1024
#define NITER 50
#define EPS   0.05f
#define MMASS 0.95f

// ---------------- static device scratch (no allocations allowed) ------------
__device__ __align__(16) float          g_M  [BN * BN];          // 4 MB
__device__ __align__(16) __nv_bfloat16  g_Abf[BN * BN];          // 2 MB
__device__ __align__(16) __nv_bfloat16  g_Tbf[BN * BN];          // 2 MB
__device__ __align__(16) float g_na[BN],    g_nt[BN];
__device__ __align__(16) float g_alpha[BN], g_beta[BN];
__device__ __align__(16) float g_maxp[NBLK], g_sump[NBLK];
__device__ __align__(16) float g_s2p [NBLK], g_lossp[NBLK];
__device__ unsigned           g_barcnt  = 0;
__device__ volatile unsigned  g_barphase = 0;

// ---------------- grid barrier (monotone phase; survives graph replays) -----
__device__ __forceinline__ void gridbar(unsigned &eph) {
    __syncthreads();
    if (threadIdx.x == 0) {
        eph++;
        __threadfence();
        unsigned old = atomicAdd(&g_barcnt, 1u);
        if (old == NBLK - 1u) {
            g_barcnt = 0;
            __threadfence();
            g_barphase = eph;
        } else {
            while (g_barphase < eph) { }
        }
        __threadfence();
    }
    __syncthreads();
}

__device__ __forceinline__ float warp_sum(float v) {
    #pragma unroll
    for (int s = 16; s; s >>= 1) v += __shfl_xor_sync(0xffffffffu, v, s);
    return v;
}
__device__ __forceinline__ float warp_max(float v) {
    #pragma unroll
    for (int s = 16; s; s >>= 1) v = fmaxf(v, __shfl_xor_sync(0xffffffffu, v, s));
    return v;
}
// deterministic 128-partial sum, executed identically by any warp
__device__ __forceinline__ float red128_sum(const float* p, int lane) {
    float s = __ldcg(p + lane) + __ldcg(p + lane + 32)
            + __ldcg(p + lane + 64) + __ldcg(p + lane + 96);
    return warp_sum(s);
}
__device__ __forceinline__ float red128_max(const float* p, int lane) {
    float s = fmaxf(fmaxf(__ldcg(p + lane), __ldcg(p + lane + 32)),
                    fmaxf(__ldcg(p + lane + 64), __ldcg(p + lane + 96)));
    return warp_max(s);
}
// warp-cooperative 1024-dot (row and vec both in smem); result in all lanes
__device__ __forceinline__ float rowdot(const float* __restrict__ row,
                                        const float* __restrict__ vec, int lane) {
    const float4* r4 = (const float4*)row;
    const float4* v4 = (const float4*)vec;
    float acc = 0.f;
    #pragma unroll
    for (int q = 0; q < 8; q++) {
        float4 a = r4[q * 32 + lane];
        float4 b = v4[q * 32 + lane];
        acc = fmaf(a.x, b.x, acc); acc = fmaf(a.y, b.y, acc);
        acc = fmaf(a.z, b.z, acc); acc = fmaf(a.w, b.w, acc);
    }
    return warp_sum(acc);
}

__global__ void __launch_bounds__(NTHR, 1)
potloss_kernel(const float* __restrict__ A, const float* __restrict__ T,
               float* __restrict__ out)
{
    extern __shared__ float sm[];
    float* smK0  = sm;           // 8192 floats: 8 K0 rows   (reused as 128x64 D tile in P1)
    float* smK0T = sm + 8192;    // 8192 floats: 8 K0^T rows
    float* smvec = sm + 16384;   // 1024 floats: alpha/beta broadcast
    __shared__ float s_warp[8];
    __shared__ float s_bcast;

    const int b = blockIdx.x, tid = threadIdx.x;
    const int w = tid >> 5, lane = tid & 31;
    unsigned eph = 0;
    if (tid == 0) eph = g_barphase;

    // ============ P0: bf16 convert + squared row norms (16 rows / block) ====
    #pragma unroll
    for (int rr = 0; rr < 2; rr++) {
        int idx = b * 16 + w * 2 + rr;                       // 0..2047
        int row; const float* src; __nv_bfloat16* dst; float* ndst;
        if (idx < BN) { row = idx;      src = A + (size_t)row * BN; dst = g_Abf + (size_t)row * BN; ndst = g_na; }
        else          { row = idx - BN; src = T + (size_t)row * BN; dst = g_Tbf + (size_t)row * BN; ndst = g_nt; }
        const float4* s4 = (const float4*)src;
        __nv_bfloat162* d2 = (__nv_bfloat162*)dst;
        float nrm = 0.f;
        #pragma unroll
        for (int q = 0; q < 8; q++) {
            int c4 = q * 32 + lane;
            float4 v = s4[c4];
            nrm = fmaf(v.x, v.x, fmaf(v.y, v.y, fmaf(v.z, v.z, fmaf(v.w, v.w, nrm))));
            d2[c4 * 2]     = __floats2bfloat162_rn(v.x, v.y);
            d2[c4 * 2 + 1] = __floats2bfloat162_rn(v.z, v.w);
        }
        nrm = warp_sum(nrm);
        if (lane == 0) __stcg(&ndst[row], nrm);
    }
    gridbar(eph);

    // ============ P1: D = A*T^T (bf16 wmma) -> M = relu(na+nt-2D), max(M) ===
    const int tm = (b >> 4) * 128;
    const int tn = (b & 15) * 64;
    {
        const int wm = w >> 1, wn = w & 1;
        wmma::fragment<wmma::accumulator, 16, 16, 16, float> c[2][2];
        #pragma unroll
        for (int mi = 0; mi < 2; mi++)
            #pragma unroll
            for (int ni = 0; ni < 2; ni++) wmma::fill_fragment(c[mi][ni], 0.f);

        #pragma unroll 1
        for (int k = 0; k < BN; k += 16) {
            wmma::fragment<wmma::matrix_a, 16, 16, 16, __nv_bfloat16, wmma::row_major> af[2];
            wmma::fragment<wmma::matrix_b, 16, 16, 16, __nv_bfloat16, wmma::col_major> bf[2];
            #pragma unroll
            for (int mi = 0; mi < 2; mi++)
                wmma::load_matrix_sync(af[mi], g_Abf + (size_t)(tm + wm * 32 + mi * 16) * BN + k, BN);
            #pragma unroll
            for (int ni = 0; ni < 2; ni++)
                wmma::load_matrix_sync(bf[ni], g_Tbf + (size_t)(tn + wn * 32 + ni * 16) * BN + k, BN);
            #pragma unroll
            for (int mi = 0; mi < 2; mi++)
                #pragma unroll
                for (int ni = 0; ni < 2; ni++)
                    wmma::mma_sync(c[mi][ni], af[mi], bf[ni], c[mi][ni]);
        }
        #pragma unroll
        for (int mi = 0; mi < 2; mi++)
            #pragma unroll
            for (int ni = 0; ni < 2; ni++)
                wmma::store_matrix_sync(&smK0[(wm * 32 + mi * 16) * 64 + wn * 32 + ni * 16],
                                        c[mi][ni], 64, wmma::mem_row_major);
        __syncthreads();

        float lmax = 0.f;
        #pragma unroll 1
        for (int f = tid; f < 2048; f += NTHR) {             // float4 units of 128x64 tile
            int r = f >> 4, c4 = f & 15;
            float4 d  = ((const float4*)smK0)[f];
            float nai = __ldcg(&g_na[tm + r]);
            float4 nt4 = __ldcg(((const float4*)g_nt) + (tn >> 2) + c4);
            float4 mv;
            mv.x = fmaxf(nai + nt4.x - 2.f * d.x, 0.f);
            mv.y = fmaxf(nai + nt4.y - 2.f * d.y, 0.f);
            mv.z = fmaxf(nai + nt4.z - 2.f * d.z, 0.f);
            mv.w = fmaxf(nai + nt4.w - 2.f * d.w, 0.f);
            lmax = fmaxf(lmax, fmaxf(fmaxf(mv.x, mv.y), fmaxf(mv.z, mv.w)));
            __stcg(((float4*)(g_M + (size_t)(tm + r) * BN + tn)) + c4, mv);
        }
        lmax = warp_max(lmax);
        if (lane == 0) s_warp[w] = lmax;
        __syncthreads();
        if (tid == 0) {
            float mx = s_warp[0];
            #pragma unroll
            for (int k = 1; k < 8; k++) mx = fmaxf(mx, s_warp[k]);
            __stcg(&g_maxp[b], mx);
        }
    }
    gridbar(eph);

    // ============ P2: K0 rows + K0^T rows -> smem; sum(K0) partials =========
    if (w == 0) {
        float mx = red128_max(g_maxp, lane);
        if (lane == 0) s_bcast = mx;
    }
    __syncthreads();
    const float kscale = 1.0f / (s_bcast * EPS);
    {
        const int i = b * 8 + w;                              // owned row == owned col
        const float4* mrow = (const float4*)(g_M + (size_t)i * BN);
        float4* krow = (float4*)(smK0 + w * BN);
        float psum = 0.f;
        #pragma unroll
        for (int q = 0; q < 8; q++) {
            float4 mv = __ldcg(mrow + q * 32 + lane);
            float4 kv;
            kv.x = __expf(-mv.x * kscale); kv.y = __expf(-mv.y * kscale);
            kv.z = __expf(-mv.z * kscale); kv.w = __expf(-mv.w * kscale);
            psum += kv.x + kv.y + kv.z + kv.w;
            krow[q * 32 + lane] = kv;
        }
        psum = warp_sum(psum);
        if (lane == 0) s_warp[w] = psum;
        #pragma unroll 1
        for (int i2 = lane; i2 < BN; i2 += 32)                // column i of K0
            smK0T[w * BN + i2] = __expf(-__ldcg(&g_M[(size_t)i2 * BN + i]) * kscale);
    }
    __syncthreads();
    if (tid == 0) {
        float s = 0.f;
        #pragma unroll
        for (int k = 0; k < 8; k++) s += s_warp[k];
        __stcg(&g_sump[b], s);
    }
    if (tid < 8) { __stcg(&g_alpha[b * 8 + tid], 1.f); __stcg(&g_beta[b * 8 + tid], 1.f); }
    gridbar(eph);

    if (w == 0) {
        float s = red128_sum(g_sump, lane);
        if (lane == 0) s_bcast = s;
    }
    __syncthreads();
    float g = MMASS / s_bcast;                                // m / sum(K0raw)

    // ============ 50 Dykstra iterations (rank-1 state in registers) =========
    const float ab = 1.0f / (float)BN;                        // a_i = b_j = 1/B
    float alpha_i = 1.f, u_i = 1.f, beta_j = 1.f, v_j = 1.f;

    #pragma unroll 1
    for (int it = 0; it < NITER; it++) {
        // ---- row pass: y = K0 * beta ----
        ((float4*)smvec)[tid] = __ldcg(((const float4*)g_beta) + tid);
        __syncthreads();
        float y = rowdot(smK0 + w * BN, smvec, lane);
        float r = fminf(ab / (g * alpha_i * u_i * y), 1.f);
        alpha_i *= r * u_i;
        u_i = 1.f / r;
        if (lane == 0) __stcg(&g_alpha[b * 8 + w], alpha_i);
        gridbar(eph);

        // ---- col pass: z = K0^T * alpha ----
        ((float4*)smvec)[tid] = __ldcg(((const float4*)g_alpha) + tid);
        __syncthreads();
        float z = rowdot(smK0T + w * BN, smvec, lane);
        float t = g * v_j * beta_j * z;                       // colsum_j(K1p)
        float c = fminf(ab / t, 1.f);
        beta_j *= c * v_j;
        v_j = 1.f / c;
        if (lane == 0) {
            __stcg(&g_beta[b * 8 + w], beta_j);
            s_warp[w] = c * t;                                // colsum_j(K2)
        }
        __syncthreads();
        if (tid == 0) {
            float s = 0.f;
            #pragma unroll
            for (int k = 0; k < 8; k++) s += s_warp[k];
            __stcg(&g_s2p[b], s);
        }
        gridbar(eph);

        // ---- mass pass: g *= m / sum(K2)  (identical in every block) ----
        if (w == 0) {
            float s = red128_sum(g_s2p, lane);
            if (lane == 0) s_bcast = s;
        }
        __syncthreads();
        g *= MMASS / s_bcast;
    }

    // ============ loss: mean_i( logsumexp_j(pi_ij) - pi_ii ) ================
    ((float4*)smvec)[tid] = __ldcg(((const float4*)g_beta) + tid);
    __syncthreads();
    {
        const int i = b * 8 + w;
        const float ga = g * alpha_i;
        const float* krow = smK0 + w * BN;
        float se = 0.f;
        #pragma unroll 1
        for (int jj = lane; jj < BN; jj += 32)
            se += __expf(ga * krow[jj] * smvec[jj]);
        se = warp_sum(se);
        float pii = ga * krow[i] * smvec[i];
        if (lane == 0) s_warp[w] = logf(se) - pii;
    }
    __syncthreads();
    if (tid == 0) {
        float s = 0.f;
        #pragma unroll
        for (int k = 0; k < 8; k++) s += s_warp[k];
        __stcg(&g_lossp[b], s);
    }
    gridbar(eph);

    if (b == 0 && w == 0) {
        float s = red128_sum(g_lossp, lane);
        if (lane == 0) out[0] = s * (1.0f / (float)BN);
    }
}

extern "C" void kernel_launch(void* const* d_in, const int* in_sizes, int n_in,
                              void* d_out, int out_size) {
    (void)in_sizes; (void)n_in; (void)out_size;
    const float* A = (const float*)d_in[0];
    const float* T = (const float*)d_in[1];
    float* out = (float*)d_out;
    static_assert(sizeof(float) * 17408 == 69632, "smem layout");
    cudaFuncSetAttribute(potloss_kernel,
                         cudaFuncAttributeMaxDynamicSharedMemorySize, 69632);
    potloss_kernel<<<NBLK, NTHR, 69632>>>(A, T, out);
}

// round 6
// speedup vs baseline: 1.1280x; 1.1280x over previous
#include <cuda_runtime.h>
#include <cuda_bf16.h>
#include <mma.h>

using namespace nvcuda;

#define BN     1024
#define NITER  50
#define EPS    0.05f
#define MMASS  0.95f
#define NB_IT  64        // iteration kernel blocks
#define NT_IT  512       // 16 warps: 16 rows + 16 cols per block

// ---------------- static device scratch (no allocations allowed) ------------
__device__ __align__(16) float          g_M  [BN * BN];     // 4 MB
__device__ __align__(16) float          g_MT [BN * BN];     // 4 MB (transpose)
__device__ __align__(16) __nv_bfloat16  g_Abf[BN * BN];     // 2 MB
__device__ __align__(16) __nv_bfloat16  g_Tbf[BN * BN];     // 2 MB
__device__ __align__(16) float g_na[BN],    g_nt[BN];
__device__ __align__(16) float g_alpha[BN], g_beta[BN];
__device__ __align__(16) float g_maxp[128];
__device__ __align__(16) float g_sump[NB_IT], g_s2p[NB_IT], g_lossp[NB_IT];
__device__ volatile unsigned  g_flag[NB_IT];                // zero-init

// ---------------- warp helpers ---------------------------------------------
__device__ __forceinline__ float warp_sum(float v) {
    #pragma unroll
    for (int s = 16; s; s >>= 1) v += __shfl_xor_sync(0xffffffffu, v, s);
    return v;
}
__device__ __forceinline__ float warp_max(float v) {
    #pragma unroll
    for (int s = 16; s; s >>= 1) v = fmaxf(v, __shfl_xor_sync(0xffffffffu, v, s));
    return v;
}
__device__ __forceinline__ float red128_max(const float* p, int lane) {
    float s = fmaxf(fmaxf(__ldcg(p + lane), __ldcg(p + lane + 32)),
                    fmaxf(__ldcg(p + lane + 64), __ldcg(p + lane + 96)));
    return warp_max(s);
}
__device__ __forceinline__ float red64_sum(const float* p, int lane) {
    float s = __ldcg(p + lane) + __ldcg(p + lane + 32);
    return warp_sum(s);
}

// -------- decentralized flag barrier over NB_IT blocks (no atomics path) ----
__device__ __forceinline__ void flagbar(unsigned& eph, int b, int tid, int lane) {
    __syncthreads();                      // all block work (incl. stcg data) done
    eph++;                                // every thread tracks the phase
    if (tid == 0) {
        __threadfence();                  // data -> visible before flag
        atomicExch((unsigned*)&g_flag[b], eph);
    }
    if (tid < 32) {
        for (;;) {
            unsigned f0 = g_flag[lane];
            unsigned f1 = g_flag[lane + 32];
            bool ok = (f0 >= eph) && (f1 >= eph);
            if (__all_sync(0xffffffffu, ok)) break;
        }
        __threadfence();                  // acquire
    }
    __syncthreads();
}

// -------- bf16 dot: 1024-elem row . vec, both bf16 in smem ------------------
__device__ __forceinline__ float fma2(unsigned a, unsigned b, float acc) {
    float2 fa = __bfloat1622float2(*(const __nv_bfloat162*)&a);
    float2 fb = __bfloat1622float2(*(const __nv_bfloat162*)&b);
    acc = fmaf(fa.x, fb.x, acc);
    return fmaf(fa.y, fb.y, acc);
}
__device__ __forceinline__ float dotb(const __nv_bfloat162* __restrict__ row,
                                      const __nv_bfloat162* __restrict__ vec,
                                      int lane) {
    const uint4* r4 = (const uint4*)row;
    const uint4* v4 = (const uint4*)vec;
    float acc = 0.f;
    #pragma unroll
    for (int q = 0; q < 4; q++) {
        uint4 a = r4[q * 32 + lane];
        uint4 b = v4[q * 32 + lane];
        acc = fma2(a.x, b.x, acc); acc = fma2(a.y, b.y, acc);
        acc = fma2(a.z, b.z, acc); acc = fma2(a.w, b.w, acc);
    }
    return warp_sum(acc);
}

// ===================== K1: fp32 -> bf16 + row norms =========================
__global__ void __launch_bounds__(256)
k_convert(const float* __restrict__ A, const float* __restrict__ T) {
    const int b = blockIdx.x, tid = threadIdx.x;
    const int w = tid >> 5, lane = tid & 31;
    const int idx = b * 8 + w;                       // 0..2047
    int row; const float* src; __nv_bfloat16* dst; float* ndst;
    if (idx < BN) { row = idx;      src = A + (size_t)row * BN; dst = g_Abf + (size_t)row * BN; ndst = g_na; }
    else          { row = idx - BN; src = T + (size_t)row * BN; dst = g_Tbf + (size_t)row * BN; ndst = g_nt; }
    const float4* s4 = (const float4*)src;
    __nv_bfloat162* d2 = (__nv_bfloat162*)dst;
    float nrm = 0.f;
    #pragma unroll
    for (int q = 0; q < 8; q++) {
        int c4 = q * 32 + lane;
        float4 v = s4[c4];
        nrm = fmaf(v.x, v.x, fmaf(v.y, v.y, fmaf(v.z, v.z, fmaf(v.w, v.w, nrm))));
        d2[c4 * 2]     = __floats2bfloat162_rn(v.x, v.y);
        d2[c4 * 2 + 1] = __floats2bfloat162_rn(v.z, v.w);
    }
    nrm = warp_sum(nrm);
    if (lane == 0) __stcg(&ndst[row], nrm);
}

// ===================== K2: GEMM -> M, M^T, per-block max ====================
#define DT_PITCH 68
__global__ void __launch_bounds__(256)
k_gemm() {
    __shared__ float dt[128 * DT_PITCH];     // 34.8 KB, padded vs bank conflicts
    __shared__ float s_warp[8];
    const int b = blockIdx.x, tid = threadIdx.x;
    const int w = tid >> 5, lane = tid & 31;
    const int tm = (b >> 4) * 128;
    const int tn = (b & 15) * 64;
    const int wm = w >> 1, wn = w & 1;

    wmma::fragment<wmma::accumulator, 16, 16, 16, float> c[2][2];
    #pragma unroll
    for (int mi = 0; mi < 2; mi++)
        #pragma unroll
        for (int ni = 0; ni < 2; ni++) wmma::fill_fragment(c[mi][ni], 0.f);

    #pragma unroll 1
    for (int k = 0; k < BN; k += 16) {
        wmma::fragment<wmma::matrix_a, 16, 16, 16, __nv_bfloat16, wmma::row_major> af[2];
        wmma::fragment<wmma::matrix_b, 16, 16, 16, __nv_bfloat16, wmma::col_major> bf[2];
        #pragma unroll
        for (int mi = 0; mi < 2; mi++)
            wmma::load_matrix_sync(af[mi], g_Abf + (size_t)(tm + wm * 32 + mi * 16) * BN + k, BN);
        #pragma unroll
        for (int ni = 0; ni < 2; ni++)
            wmma::load_matrix_sync(bf[ni], g_Tbf + (size_t)(tn + wn * 32 + ni * 16) * BN + k, BN);
        #pragma unroll
        for (int mi = 0; mi < 2; mi++)
            #pragma unroll
            for (int ni = 0; ni < 2; ni++)
                wmma::mma_sync(c[mi][ni], af[mi], bf[ni], c[mi][ni]);
    }
    #pragma unroll
    for (int mi = 0; mi < 2; mi++)
        #pragma unroll
        for (int ni = 0; ni < 2; ni++)
            wmma::store_matrix_sync(&dt[(wm * 32 + mi * 16) * DT_PITCH + wn * 32 + ni * 16],
                                    c[mi][ni], DT_PITCH, wmma::mem_row_major);
    __syncthreads();

    // M = relu(na + nt - 2D); write M rows; overwrite dt in place with M; max
    float lmax = 0.f;
    #pragma unroll 1
    for (int f = tid; f < 2048; f += 256) {
        int r = f >> 4, c4 = f & 15;
        float4 d = *(const float4*)&dt[r * DT_PITCH + c4 * 4];
        float  nai = __ldcg(&g_na[tm + r]);
        float4 nt4 = __ldcg(((const float4*)g_nt) + (tn >> 2) + c4);
        float4 mv;
        mv.x = fmaxf(nai + nt4.x - 2.f * d.x, 0.f);
        mv.y = fmaxf(nai + nt4.y - 2.f * d.y, 0.f);
        mv.z = fmaxf(nai + nt4.z - 2.f * d.z, 0.f);
        mv.w = fmaxf(nai + nt4.w - 2.f * d.w, 0.f);
        lmax = fmaxf(lmax, fmaxf(fmaxf(mv.x, mv.y), fmaxf(mv.z, mv.w)));
        *(float4*)&dt[r * DT_PITCH + c4 * 4] = mv;
        __stcg(((float4*)(g_M + (size_t)(tm + r) * BN + tn)) + c4, mv);
    }
    lmax = warp_max(lmax);
    if (lane == 0) s_warp[w] = lmax;
    __syncthreads();

    // transposed write: M^T[(tn+c)][tm + r], coalesced 128B stores
    #pragma unroll 1
    for (int cc = w; cc < 64; cc += 8) {
        float v0 = dt[(lane     ) * DT_PITCH + cc];
        float v1 = dt[(lane + 32) * DT_PITCH + cc];
        float v2 = dt[(lane + 64) * DT_PITCH + cc];
        float v3 = dt[(lane + 96) * DT_PITCH + cc];
        float* mtrow = g_MT + (size_t)(tn + cc) * BN + tm;
        __stcg(&mtrow[lane],      v0);
        __stcg(&mtrow[lane + 32], v1);
        __stcg(&mtrow[lane + 64], v2);
        __stcg(&mtrow[lane + 96], v3);
    }
    if (tid == 0) {
        float mx = s_warp[0];
        #pragma unroll
        for (int k = 1; k < 8; k++) mx = fmaxf(mx, s_warp[k]);
        __stcg(&g_maxp[b], mx);
    }
}

// ===================== K3: persistent iteration kernel ======================
__global__ void __launch_bounds__(NT_IT, 1)
k_iter(float* __restrict__ out) {
    extern __shared__ __align__(16) char smraw[];
    __nv_bfloat162* smK0  = (__nv_bfloat162*)smraw;      // 16 rows x 512 pairs (32 KB)
    __nv_bfloat162* smK0T = smK0  + 16 * 512;            // 32 KB
    __nv_bfloat162* smv   = smK0T + 16 * 512;            // 2 KB
    __shared__ float s_warp[16];
    __shared__ float s_b;

    const int b = blockIdx.x, tid = threadIdx.x;
    const int w = tid >> 5, lane = tid & 31;
    const int i = b * 16 + w;                            // owned row == owned col
    unsigned eph = g_flag[b];                            // monotone across replays

    // ---- kscale from 128 GEMM partial maxima ----
    if (w == 0) {
        float mx = red128_max(g_maxp, lane);
        if (lane == 0) s_b = mx;
    }
    __syncthreads();
    const float kscale = 1.0f / (s_b * EPS);

    // ---- build K0 row i and K0^T row i (bf16, smem); partial sum(K0) ----
    {
        const float4* mr  = (const float4*)(g_M  + (size_t)i * BN);
        const float4* mtr = (const float4*)(g_MT + (size_t)i * BN);
        __nv_bfloat162* kr  = smK0  + w * 512;
        __nv_bfloat162* ktr = smK0T + w * 512;
        float ps = 0.f;
        #pragma unroll
        for (int q = 0; q < 8; q++) {
            int t = q * 32 + lane;
            float4 m = __ldcg(mr + t);
            float e0 = __expf(-m.x * kscale), e1 = __expf(-m.y * kscale);
            float e2 = __expf(-m.z * kscale), e3 = __expf(-m.w * kscale);
            ps += (e0 + e1) + (e2 + e3);
            kr[t * 2]     = __floats2bfloat162_rn(e0, e1);
            kr[t * 2 + 1] = __floats2bfloat162_rn(e2, e3);
            float4 mt = __ldcg(mtr + t);
            ktr[t * 2]     = __floats2bfloat162_rn(__expf(-mt.x * kscale), __expf(-mt.y * kscale));
            ktr[t * 2 + 1] = __floats2bfloat162_rn(__expf(-mt.z * kscale), __expf(-mt.w * kscale));
        }
        ps = warp_sum(ps);
        if (lane == 0) s_warp[w] = ps;
    }
    if (tid < 16) { __stcg(&g_alpha[b * 16 + tid], 1.f); __stcg(&g_beta[b * 16 + tid], 1.f); }
    __syncthreads();
    if (tid == 0) {
        float s = 0.f;
        #pragma unroll
        for (int k = 0; k < 16; k++) s += s_warp[k];
        __stcg(&g_sump[b], s);
    }
    flagbar(eph, b, tid, lane);

    if (w == 0) {
        float s = red64_sum(g_sump, lane);
        if (lane == 0) s_b = s;
    }
    __syncthreads();
    float g = MMASS / s_b;                               // m / sum(K0raw)

    // ---- 50 Dykstra iterations, rank-1 state in registers ----
    const float ab = 1.0f / (float)BN;
    float alpha = 1.f, u = 1.f, beta = 1.f, v = 1.f;

    #pragma unroll 1
    for (int it = 0; it < NITER; it++) {
        // row pass: y = K0 . beta
        float2 bv = __ldcg(((const float2*)g_beta) + tid);
        smv[tid] = __floats2bfloat162_rn(bv.x, bv.y);
        __syncthreads();
        float y = dotb(smK0 + w * 512, smv, lane);
        float r = fminf(ab / (g * alpha * u * y), 1.f);
        alpha *= r * u;
        u = 1.f / r;
        if (lane == 0) __stcg(&g_alpha[i], alpha);
        flagbar(eph, b, tid, lane);

        // col pass: z = K0^T . alpha
        float2 av = __ldcg(((const float2*)g_alpha) + tid);
        smv[tid] = __floats2bfloat162_rn(av.x, av.y);
        __syncthreads();
        float z = dotb(smK0T + w * 512, smv, lane);
        float t = g * v * beta * z;                      // colsum(K1p)
        float c = fminf(ab / t, 1.f);
        beta *= c * v;
        v = 1.f / c;
        if (lane == 0) { __stcg(&g_beta[i], beta); s_warp[w] = c * t; }
        __syncthreads();
        if (tid == 0) {
            float s = 0.f;
            #pragma unroll
            for (int k = 0; k < 16; k++) s += s_warp[k];
            __stcg(&g_s2p[b], s);
        }
        flagbar(eph, b, tid, lane);

        // mass pass (identical in every block)
        if (w == 0) {
            float s = red64_sum(g_s2p, lane);
            if (lane == 0) s_b = s;
        }
        __syncthreads();
        g *= MMASS / s_b;
    }

    // ---- loss: mean_i( logsumexp_j(pi_ij) - pi_ii ) ----
    {
        float2 bv = __ldcg(((const float2*)g_beta) + tid);
        smv[tid] = __floats2bfloat162_rn(bv.x, bv.y);
        __syncthreads();
        const __nv_bfloat162* row = smK0 + w * 512;
        const float ga = g * alpha;
        float se = 0.f;
        #pragma unroll 1
        for (int t = lane; t < 512; t += 32) {
            float2 k2 = __bfloat1622float2(row[t]);
            float2 b2 = __bfloat1622float2(smv[t]);
            se += __expf(ga * k2.x * b2.x) + __expf(ga * k2.y * b2.y);
        }
        se = warp_sum(se);
        float ki = (i & 1) ? __high2float(row[i >> 1]) : __low2float(row[i >> 1]);
        float bi = (i & 1) ? __high2float(smv[i >> 1]) : __low2float(smv[i >> 1]);
        float pii = ga * ki * bi;
        if (lane == 0) s_warp[w] = logf(se) - pii;
    }
    __syncthreads();
    if (tid == 0) {
        float s = 0.f;
        #pragma unroll
        for (int k = 0; k < 16; k++) s += s_warp[k];
        __stcg(&g_lossp[b], s);
    }
    flagbar(eph, b, tid, lane);

    if (b == 0 && w == 0) {
        float s = red64_sum(g_lossp, lane);
        if (lane == 0) out[0] = s * (1.0f / (float)BN);
    }
}

// ===========================================================================
extern "C" void kernel_launch(void* const* d_in, const int* in_sizes, int n_in,
                              void* d_out, int out_size) {
    (void)in_sizes; (void)n_in; (void)out_size;
    const float* A = (const float*)d_in[0];
    const float* T = (const float*)d_in[1];
    float* out = (float*)d_out;

    const int smem_iter = (16 * 512 * 2 + 512) * (int)sizeof(__nv_bfloat162); // 67584
    cudaFuncSetAttribute(k_iter, cudaFuncAttributeMaxDynamicSharedMemorySize, smem_iter);

    k_convert<<<256, 256>>>(A, T);
    k_gemm<<<128, 256>>>();
    k_iter<<<NB_IT, NT_IT, smem_iter>>>(out);
}